// round 1
// baseline (speedup 1.0000x reference)
#include <cuda_runtime.h>
#include <cstdint>

// Problem constants
#define MB   8192
#define DIN  4096
#define RANK 2048
#define UNITS 4096

// Tiling
#define BM 128
#define BN 128
#define BK 16
#define NTHREADS 256

// Scratch for H = (X @ U) * S : [8192, 2048] fp32 (allowed: __device__ global, no cudaMalloc)
__device__ float g_H[(size_t)MB * RANK];

// ---- packed f32x2 helpers (Blackwell sm_103a) ----
__device__ __forceinline__ unsigned long long pack2(float lo, float hi) {
    unsigned long long r;
    asm("mov.b64 %0, {%1, %2};" : "=l"(r) : "r"(__float_as_uint(lo)), "r"(__float_as_uint(hi)));
    return r;
}
__device__ __forceinline__ void fma2(unsigned long long& d, unsigned long long a, unsigned long long b) {
    asm("fma.rn.f32x2 %0, %1, %2, %0;" : "+l"(d) : "l"(a), "l"(b));
}
__device__ __forceinline__ unsigned long long mul2(unsigned long long a, unsigned long long b) {
    unsigned long long r;
    asm("mul.rn.f32x2 %0, %1, %2;" : "=l"(r) : "l"(a), "l"(b));
    return r;
}
__device__ __forceinline__ unsigned long long add2(unsigned long long a, unsigned long long b) {
    unsigned long long r;
    asm("add.rn.f32x2 %0, %1, %2;" : "=l"(r) : "l"(a), "l"(b));
    return r;
}

// MODE 0: C = (A[M,K] @ B[K,N]) * S[N]      (B row-major [K,N]); C = g_H
// MODE 1: C = relu(A[M,K] @ B^T + bias[N])  (B row-major [N,K], i.e. V); A = g_H
template <int MODE>
__global__ void sgemm_kernel(const float* __restrict__ Ain,
                             const float* __restrict__ B,
                             const float* __restrict__ E,   // S (MODE0) or bias (MODE1)
                             float* __restrict__ Cout,
                             int M, int N, int K)
{
    __shared__ __align__(16) float As[BK][BM];
    __shared__ __align__(16) float Bs[BK][BN];

    const float* A = (MODE == 1) ? g_H : Ain;
    float*       C = (MODE == 0) ? g_H : Cout;

    const int tid = threadIdx.x;
    const int m0 = blockIdx.y * BM;
    const int n0 = blockIdx.x * BN;

    const int ty = tid >> 4;          // 0..15
    const int tx = tid & 15;          // 0..15
    const int tm0 = ty * 8;
    const int tn0 = tx * 8;

    // global-load index helpers
    const int a_row = tid >> 2;       // 0..63 (+64)
    const int a_col = (tid & 3) * 4;  // 0,4,8,12

    const int nk = K / BK;

    float4 aReg[2], bReg[2];

    // ---- prologue: load k-tile 0 into regs ----
    {
        const int k0 = 0;
#pragma unroll
        for (int i = 0; i < 2; i++) {
            int r = a_row + i * 64;
            aReg[i] = *(const float4*)(A + (size_t)(m0 + r) * K + k0 + a_col);
        }
        if (MODE == 0) {
#pragma unroll
            for (int i = 0; i < 2; i++) {
                int r = (tid >> 5) + i * 8;       // 0..15
                int c = (tid & 31) * 4;           // 0..124
                bReg[i] = *(const float4*)(B + (size_t)(k0 + r) * N + n0 + c);
            }
        } else {
#pragma unroll
            for (int i = 0; i < 2; i++) {
                int r = (tid >> 2) + i * 64;      // 0..127 (n index)
                int c = (tid & 3) * 4;            // 0..12  (k index)
                bReg[i] = *(const float4*)(B + (size_t)(n0 + r) * K + k0 + c);
            }
        }
    }

    // store regs -> smem (A transposed; B transposed for MODE 1)
#pragma unroll
    for (int i = 0; i < 2; i++) {
        int r = a_row + i * 64;
        As[a_col + 0][r] = aReg[i].x;
        As[a_col + 1][r] = aReg[i].y;
        As[a_col + 2][r] = aReg[i].z;
        As[a_col + 3][r] = aReg[i].w;
    }
    if (MODE == 0) {
#pragma unroll
        for (int i = 0; i < 2; i++) {
            int r = (tid >> 5) + i * 8;
            int c = (tid & 31) * 4;
            *(float4*)&Bs[r][c] = bReg[i];
        }
    } else {
#pragma unroll
        for (int i = 0; i < 2; i++) {
            int r = (tid >> 2) + i * 64;
            int c = (tid & 3) * 4;
            Bs[c + 0][r] = bReg[i].x;
            Bs[c + 1][r] = bReg[i].y;
            Bs[c + 2][r] = bReg[i].z;
            Bs[c + 3][r] = bReg[i].w;
        }
    }
    __syncthreads();

    // accumulators: acc[i][jp] = packed (c[i][2jp], c[i][2jp+1])
    unsigned long long acc[8][4];
#pragma unroll
    for (int i = 0; i < 8; i++)
#pragma unroll
        for (int jp = 0; jp < 4; jp++) acc[i][jp] = 0ull;

    for (int kt = 1; kt <= nk; kt++) {
        // ---- prefetch next k-tile into regs (overlaps with compute below) ----
        if (kt < nk) {
            const int k0 = kt * BK;
#pragma unroll
            for (int i = 0; i < 2; i++) {
                int r = a_row + i * 64;
                aReg[i] = *(const float4*)(A + (size_t)(m0 + r) * K + k0 + a_col);
            }
            if (MODE == 0) {
#pragma unroll
                for (int i = 0; i < 2; i++) {
                    int r = (tid >> 5) + i * 8;
                    int c = (tid & 31) * 4;
                    bReg[i] = *(const float4*)(B + (size_t)(k0 + r) * N + n0 + c);
                }
            } else {
#pragma unroll
                for (int i = 0; i < 2; i++) {
                    int r = (tid >> 2) + i * 64;
                    int c = (tid & 3) * 4;
                    bReg[i] = *(const float4*)(B + (size_t)(n0 + r) * K + k0 + c);
                }
            }
        }

        // ---- compute on current smem tile ----
#pragma unroll
        for (int kk = 0; kk < BK; kk++) {
            float a[8];
            *(float4*)&a[0] = *(const float4*)&As[kk][tm0];
            *(float4*)&a[4] = *(const float4*)&As[kk][tm0 + 4];
            unsigned long long b[4];
            *(ulonglong2*)&b[0] = *(const ulonglong2*)&Bs[kk][tn0];
            *(ulonglong2*)&b[2] = *(const ulonglong2*)&Bs[kk][tn0 + 4];
#pragma unroll
            for (int i = 0; i < 8; i++) {
                unsigned long long a2 = pack2(a[i], a[i]);
#pragma unroll
                for (int jp = 0; jp < 4; jp++) fma2(acc[i][jp], a2, b[jp]);
            }
        }

        if (kt < nk) {
            __syncthreads();
            // store prefetched regs -> smem
#pragma unroll
            for (int i = 0; i < 2; i++) {
                int r = a_row + i * 64;
                As[a_col + 0][r] = aReg[i].x;
                As[a_col + 1][r] = aReg[i].y;
                As[a_col + 2][r] = aReg[i].z;
                As[a_col + 3][r] = aReg[i].w;
            }
            if (MODE == 0) {
#pragma unroll
                for (int i = 0; i < 2; i++) {
                    int r = (tid >> 5) + i * 8;
                    int c = (tid & 31) * 4;
                    *(float4*)&Bs[r][c] = bReg[i];
                }
            } else {
#pragma unroll
                for (int i = 0; i < 2; i++) {
                    int r = (tid >> 2) + i * 64;
                    int c = (tid & 3) * 4;
                    Bs[c + 0][r] = bReg[i].x;
                    Bs[c + 1][r] = bReg[i].y;
                    Bs[c + 2][r] = bReg[i].z;
                    Bs[c + 3][r] = bReg[i].w;
                }
            }
            __syncthreads();
        }
    }

    // ---- epilogue ----
    if (MODE == 0) {
        unsigned long long s[4];
        *(ulonglong2*)&s[0] = *(const ulonglong2*)(E + n0 + tn0);
        *(ulonglong2*)&s[2] = *(const ulonglong2*)(E + n0 + tn0 + 4);
#pragma unroll
        for (int i = 0; i < 8; i++) {
            unsigned long long r[4];
#pragma unroll
            for (int jp = 0; jp < 4; jp++) r[jp] = mul2(acc[i][jp], s[jp]);
            const float* f = (const float*)r;
            float* cp = C + (size_t)(m0 + tm0 + i) * N + n0 + tn0;
            *(float4*)(cp + 0) = *(const float4*)&f[0];
            *(float4*)(cp + 4) = *(const float4*)&f[4];
        }
    } else {
        unsigned long long bb[4];
        *(ulonglong2*)&bb[0] = *(const ulonglong2*)(E + n0 + tn0);
        *(ulonglong2*)&bb[2] = *(const ulonglong2*)(E + n0 + tn0 + 4);
#pragma unroll
        for (int i = 0; i < 8; i++) {
            unsigned long long r[4];
#pragma unroll
            for (int jp = 0; jp < 4; jp++) r[jp] = add2(acc[i][jp], bb[jp]);
            float* f = (float*)r;
#pragma unroll
            for (int j = 0; j < 8; j++) f[j] = fmaxf(f[j], 0.0f);
            float* cp = C + (size_t)(m0 + tm0 + i) * N + n0 + tn0;
            *(float4*)(cp + 0) = *(const float4*)&f[0];
            *(float4*)(cp + 4) = *(const float4*)&f[4];
        }
    }
}

extern "C" void kernel_launch(void* const* d_in, const int* in_sizes, int n_in,
                              void* d_out, int out_size)
{
    const float* X    = (const float*)d_in[0];  // [8192, 4096]
    const float* U    = (const float*)d_in[1];  // [4096, 2048]
    const float* S    = (const float*)d_in[2];  // [2048]
    const float* V    = (const float*)d_in[3];  // [4096, 2048]
    const float* bias = (const float*)d_in[4];  // [4096]
    float* out = (float*)d_out;                 // [8192, 4096]

    dim3 blk(NTHREADS);

    // H = (X @ U) * S   -> g_H
    dim3 g1(RANK / BN, MB / BM);
    sgemm_kernel<0><<<g1, blk>>>(X, U, S, nullptr, MB, RANK, DIN);

    // out = relu(H @ V^T + bias)
    dim3 g2(UNITS / BN, MB / BM);
    sgemm_kernel<1><<<g2, blk>>>(nullptr, V, bias, out, MB, UNITS, RANK);
}

// round 7
// speedup vs baseline: 2.2624x; 2.2624x over previous
#include <cuda_runtime.h>
#include <cuda_bf16.h>
#include <cstdint>

#define MB_    8192
#define DIN_   4096
#define RANK_  2048
#define UNITS_ 4096

#define BM 128
#define BN 128
#define BK 32
#define NSTAGE 3
#define NTHR 512

// SMEM tile rows padded to 80B (5 x 16B) -> ldmatrix conflict-free
#define ROWB 80
#define TILEB (128 * ROWB)       /* 10240 B per tile */
#define STAGEB (4 * TILEB)       /* Ah,Al,Bh,Bl = 40960 B */
#define SMEMB (NSTAGE * STAGEB)  /* 122880 B */
#define OFF_AH 0
#define OFF_AL TILEB
#define OFF_BH (2 * TILEB)
#define OFF_BL (3 * TILEB)

// ---------------- device scratch (no cudaMalloc allowed) ----------------
__device__ __nv_bfloat16 g_Xh[(size_t)MB_ * DIN_];
__device__ __nv_bfloat16 g_Xl[(size_t)MB_ * DIN_];
__device__ __nv_bfloat16 g_Uth[(size_t)RANK_ * DIN_];   // (U*diag(S))^T, [RANK, DIN]
__device__ __nv_bfloat16 g_Utl[(size_t)RANK_ * DIN_];
__device__ __nv_bfloat16 g_Vh[(size_t)UNITS_ * RANK_];  // V already [N, K]
__device__ __nv_bfloat16 g_Vl[(size_t)UNITS_ * RANK_];
__device__ __nv_bfloat16 g_Hh[(size_t)MB_ * RANK_];
__device__ __nv_bfloat16 g_Hl[(size_t)MB_ * RANK_];

// ---------------- helpers ----------------
__device__ __forceinline__ uint32_t su32(const void* p) {
    uint32_t a;
    asm("{ .reg .u64 t; cvta.to.shared.u64 t, %1; cvt.u32.u64 %0, t; }" : "=r"(a) : "l"(p));
    return a;
}
__device__ __forceinline__ void cp16(uint32_t d, const void* g) {
    asm volatile("cp.async.cg.shared.global [%0], [%1], 16;" :: "r"(d), "l"(g));
}
__device__ __forceinline__ void ldsm4(uint32_t& r0, uint32_t& r1, uint32_t& r2, uint32_t& r3,
                                      uint32_t addr) {
    asm volatile("ldmatrix.sync.aligned.m8n8.x4.shared.b16 {%0,%1,%2,%3}, [%4];"
                 : "=r"(r0), "=r"(r1), "=r"(r2), "=r"(r3) : "r"(addr));
}
__device__ __forceinline__ void mma16816(float* c, uint32_t a0, uint32_t a1, uint32_t a2,
                                         uint32_t a3, uint32_t b0, uint32_t b1) {
    asm volatile(
        "mma.sync.aligned.m16n8k16.row.col.f32.bf16.bf16.f32 "
        "{%0,%1,%2,%3}, {%4,%5,%6,%7}, {%8,%9}, {%0,%1,%2,%3};"
        : "+f"(c[0]), "+f"(c[1]), "+f"(c[2]), "+f"(c[3])
        : "r"(a0), "r"(a1), "r"(a2), "r"(a3), "r"(b0), "r"(b1));
}
__device__ __forceinline__ uint32_t pack_hi(float x, float y) {
    __nv_bfloat162 t(__float2bfloat16(x), __float2bfloat16(y));
    return *reinterpret_cast<uint32_t*>(&t);
}
__device__ __forceinline__ uint32_t pack_lo(float x, float y) {
    __nv_bfloat16 hx = __float2bfloat16(x), hy = __float2bfloat16(y);
    __nv_bfloat162 t(__float2bfloat16(x - __bfloat162float(hx)),
                     __float2bfloat16(y - __bfloat162float(hy)));
    return *reinterpret_cast<uint32_t*>(&t);
}

// ---------------- conversion kernels ----------------
__global__ void split_kernel(const float* __restrict__ src,
                             __nv_bfloat16* __restrict__ hi,
                             __nv_bfloat16* __restrict__ lo, int n4) {
    int i = blockIdx.x * blockDim.x + threadIdx.x;
    if (i >= n4) return;
    float4 v = reinterpret_cast<const float4*>(src)[i];
    uint2 hu = { pack_hi(v.x, v.y), pack_hi(v.z, v.w) };
    uint2 lu = { pack_lo(v.x, v.y), pack_lo(v.z, v.w) };
    reinterpret_cast<uint2*>(hi)[i] = hu;
    reinterpret_cast<uint2*>(lo)[i] = lu;
}

// Ut = (U * diag(S))^T split to bf16 hi/lo.  U: [DIN, RANK] row-major.
__global__ void uprep_kernel(const float* __restrict__ U, const float* __restrict__ S) {
    __shared__ float t[32][33];
    int n0 = blockIdx.x * 32, k0 = blockIdx.y * 32;
    int tx = threadIdx.x, ty = threadIdx.y;
    float sv = S[n0 + tx];
#pragma unroll
    for (int i = 0; i < 4; i++)
        t[ty + i * 8][tx] = U[(size_t)(k0 + ty + i * 8) * RANK_ + n0 + tx] * sv;
    __syncthreads();
#pragma unroll
    for (int i = 0; i < 4; i++) {
        int n = n0 + ty + i * 8, k = k0 + tx;
        float v = t[tx][ty + i * 8];
        __nv_bfloat16 h = __float2bfloat16(v);
        __nv_bfloat16 l = __float2bfloat16(v - __bfloat162float(h));
        g_Uth[(size_t)n * DIN_ + k] = h;
        g_Utl[(size_t)n * DIN_ + k] = l;
    }
}

// ---------------- GEMM ----------------
__device__ __forceinline__ void load_stage(uint32_t st,
                                           const __nv_bfloat16* a0, const __nv_bfloat16* a1,
                                           const __nv_bfloat16* b0, const __nv_bfloat16* b1,
                                           int K, int tid) {
    const int r = tid >> 2;          // 0..127
    const int seg = tid & 3;         // 0..3 (16B chunks of 32 bf16 = 64B row)
    const uint32_t so = (uint32_t)r * ROWB + seg * 16;
    const size_t go = (size_t)r * K + seg * 8;
    cp16(st + OFF_AH + so, a0 + go);
    cp16(st + OFF_AL + so, a1 + go);
    cp16(st + OFF_BH + so, b0 + go);
    cp16(st + OFF_BL + so, b1 + go);
    asm volatile("cp.async.commit_group;" ::: "memory");
}

template <int MODE>
__global__ void __launch_bounds__(NTHR, 1)
gemm_kernel(const float* __restrict__ bias, float* __restrict__ out) {
    constexpr int K = (MODE == 0) ? DIN_ : RANK_;
    constexpr int NC = K / BK;

    extern __shared__ __align__(128) char smem[];
    const uint32_t sb = su32(smem);
    const int tid = threadIdx.x;
    const int lane = tid & 31;
    const int warp = tid >> 5;
    const int wm = warp >> 2;        // 0..3
    const int wn = warp & 3;         // 0..3
    const size_t m0 = (size_t)blockIdx.y * BM;
    const size_t n0 = (size_t)blockIdx.x * BN;

    const __nv_bfloat16 *Ah, *Al, *Bh, *Bl;
    if (MODE == 0) { Ah = g_Xh; Al = g_Xl; Bh = g_Uth; Bl = g_Utl; }
    else           { Ah = g_Hh; Al = g_Hl; Bh = g_Vh;  Bl = g_Vl;  }
    const __nv_bfloat16* a0 = Ah + m0 * K;
    const __nv_bfloat16* a1 = Al + m0 * K;
    const __nv_bfloat16* b0 = Bh + n0 * K;
    const __nv_bfloat16* b1 = Bl + n0 * K;

    // prologue: chunks 0 and 1
    load_stage(sb + 0 * STAGEB, a0, a1, b0, b1, K, tid);
    load_stage(sb + 1 * STAGEB, a0 + BK, a1 + BK, b0 + BK, b1 + BK, K, tid);

    float acc[2][4][4];
#pragma unroll
    for (int i = 0; i < 2; i++)
#pragma unroll
        for (int j = 0; j < 4; j++)
#pragma unroll
            for (int q = 0; q < 4; q++) acc[i][j][q] = 0.0f;

    // ldmatrix lane geometry (same for A and B tiles)
    const int lrow = lane & 15;          // row within 16-row ldmatrix block
    const int lhalf = (lane >> 4) * 16;  // byte offset of k-half (8 bf16)

    // incrementally-maintained ring bases (avoid % in the hot loop)
    uint32_t curStage = sb;                       // stage of chunk c
    uint32_t pfStage  = sb + 2 * STAGEB;          // stage of chunk c+2
    const uint32_t ringEnd = sb + NSTAGE * STAGEB;

    const uint32_t aLane = (uint32_t)(wm * 32 + lrow) * ROWB + lhalf;
    const uint32_t bLane = (uint32_t)(wn * 32 + lrow) * ROWB + lhalf;

    for (int c = 0; c < NC; c++) {
        if (c + 1 < NC) asm volatile("cp.async.wait_group 1;" ::: "memory");
        else            asm volatile("cp.async.wait_group 0;" ::: "memory");
        __syncthreads();

        if (c + 2 < NC) {
            const int kn = (c + 2) * BK;
            load_stage(pfStage, a0 + kn, a1 + kn, b0 + kn, b1 + kn, K, tid);
        }
        pfStage += STAGEB; if (pfStage == ringEnd) pfStage = sb;

        const uint32_t aBase = curStage + aLane;
        const uint32_t bBase = curStage + bLane;
        curStage += STAGEB; if (curStage == ringEnd) curStage = sb;

#pragma unroll
        for (int ks = 0; ks < 2; ks++) {
            const uint32_t ko = ks * 32;   // bytes: 16 bf16 per k-step
            uint32_t ah[8], al[8], bh[8], bl[8];
            // A frags: mt=0 rows 0-15, mt=1 rows 16-31
            ldsm4(ah[0], ah[1], ah[2], ah[3], aBase + OFF_AH + ko);
            ldsm4(ah[4], ah[5], ah[6], ah[7], aBase + OFF_AH + 16 * ROWB + ko);
            ldsm4(al[0], al[1], al[2], al[3], aBase + OFF_AL + ko);
            ldsm4(al[4], al[5], al[6], al[7], aBase + OFF_AL + 16 * ROWB + ko);
            // B frags: n-tile pairs (0,1) and (2,3)
            ldsm4(bh[0], bh[1], bh[2], bh[3], bBase + OFF_BH + ko);
            ldsm4(bh[4], bh[5], bh[6], bh[7], bBase + OFF_BH + 16 * ROWB + ko);
            ldsm4(bl[0], bl[1], bl[2], bl[3], bBase + OFF_BL + ko);
            ldsm4(bl[4], bl[5], bl[6], bl[7], bBase + OFF_BL + 16 * ROWB + ko);

#pragma unroll
            for (int mt = 0; mt < 2; mt++) {
                const uint32_t* A4 = &ah[mt * 4];
                const uint32_t* A4l = &al[mt * 4];
#pragma unroll
                for (int nt = 0; nt < 4; nt++) {
                    // pair p = nt>>1 selects ldsm4 group; odd nt uses regs {1,3}
                    const uint32_t bb0 = bh[(nt >> 1) * 4 + (nt & 1)];
                    const uint32_t bb1 = bh[(nt >> 1) * 4 + (nt & 1) + 2];
                    const uint32_t cb0 = bl[(nt >> 1) * 4 + (nt & 1)];
                    const uint32_t cb1 = bl[(nt >> 1) * 4 + (nt & 1) + 2];
                    float* cc = acc[mt][nt];
                    mma16816(cc, A4[0], A4[1], A4[2], A4[3], bb0, bb1);     // Ah*Bh
                    mma16816(cc, A4l[0], A4l[1], A4l[2], A4l[3], bb0, bb1); // Al*Bh
                    mma16816(cc, A4[0], A4[1], A4[2], A4[3], cb0, cb1);     // Ah*Bl
                }
            }
        }
    }

    // ---------------- epilogue ----------------
    const int crow = lane >> 2;          // 0..7
    const int ccol = (lane & 3) * 2;     // 0,2,4,6
#pragma unroll
    for (int mt = 0; mt < 2; mt++) {
#pragma unroll
        for (int nt = 0; nt < 4; nt++) {
            const float* cc = acc[mt][nt];
            const size_t m = m0 + wm * 32 + mt * 16 + crow;
            const size_t n = n0 + wn * 32 + nt * 8 + ccol;
            if (MODE == 0) {
                *reinterpret_cast<uint32_t*>(g_Hh + m * RANK_ + n) = pack_hi(cc[0], cc[1]);
                *reinterpret_cast<uint32_t*>(g_Hl + m * RANK_ + n) = pack_lo(cc[0], cc[1]);
                *reinterpret_cast<uint32_t*>(g_Hh + (m + 8) * RANK_ + n) = pack_hi(cc[2], cc[3]);
                *reinterpret_cast<uint32_t*>(g_Hl + (m + 8) * RANK_ + n) = pack_lo(cc[2], cc[3]);
            } else {
                const float bv0 = __ldg(bias + n), bv1 = __ldg(bias + n + 1);
                float2 o0 = { fmaxf(cc[0] + bv0, 0.0f), fmaxf(cc[1] + bv1, 0.0f) };
                float2 o1 = { fmaxf(cc[2] + bv0, 0.0f), fmaxf(cc[3] + bv1, 0.0f) };
                *reinterpret_cast<float2*>(out + m * UNITS_ + n) = o0;
                *reinterpret_cast<float2*>(out + (m + 8) * UNITS_ + n) = o1;
            }
        }
    }
}

// ---------------- launch ----------------
extern "C" void kernel_launch(void* const* d_in, const int* in_sizes, int n_in,
                              void* d_out, int out_size) {
    const float* X    = (const float*)d_in[0];
    const float* U    = (const float*)d_in[1];
    const float* S    = (const float*)d_in[2];
    const float* V    = (const float*)d_in[3];
    const float* bias = (const float*)d_in[4];
    float* out = (float*)d_out;

    void *pXh, *pXl, *pVh, *pVl;
    cudaGetSymbolAddress(&pXh, g_Xh);
    cudaGetSymbolAddress(&pXl, g_Xl);
    cudaGetSymbolAddress(&pVh, g_Vh);
    cudaGetSymbolAddress(&pVl, g_Vl);

    split_kernel<<<(MB_ * DIN_ / 4 + 255) / 256, 256>>>(
        X, (__nv_bfloat16*)pXh, (__nv_bfloat16*)pXl, MB_ * DIN_ / 4);
    split_kernel<<<(UNITS_ * RANK_ / 4 + 255) / 256, 256>>>(
        V, (__nv_bfloat16*)pVh, (__nv_bfloat16*)pVl, UNITS_ * RANK_ / 4);
    uprep_kernel<<<dim3(RANK_ / 32, DIN_ / 32), dim3(32, 8)>>>(U, S);

    cudaFuncSetAttribute(gemm_kernel<0>, cudaFuncAttributeMaxDynamicSharedMemorySize, SMEMB);
    cudaFuncSetAttribute(gemm_kernel<1>, cudaFuncAttributeMaxDynamicSharedMemorySize, SMEMB);

    // GEMM1: H = (X @ U) * S  (S folded into U^T), split-stored to g_Hh/g_Hl
    gemm_kernel<0><<<dim3(RANK_ / BN, MB_ / BM), NTHR, SMEMB>>>(nullptr, nullptr);
    // GEMM2: out = relu(H @ V^T + bias)
    gemm_kernel<1><<<dim3(UNITS_ / BN, MB_ / BM), NTHR, SMEMB>>>(bias, out);
}

// round 10
// speedup vs baseline: 2.3518x; 1.0395x over previous
#include <cuda_runtime.h>
#include <cuda_bf16.h>
#include <cstdint>

#define MB_    8192
#define DIN_   4096
#define RANK_  2048
#define UNITS_ 4096

#define BM 128
#define BN 128
#define BK 32
#define NSTAGE 2
#define NTHR 256

// SMEM tile rows padded to 80B (5 x 16B) -> ldmatrix conflict-free
#define ROWB 80
#define TILEB (128 * ROWB)       /* 10240 B per tile */
#define STAGEB (4 * TILEB)       /* Ah,Al,Bh,Bl = 40960 B */
#define SMEMB (NSTAGE * STAGEB)  /* 81920 B */
#define OFF_AH 0
#define OFF_AL TILEB
#define OFF_BH (2 * TILEB)
#define OFF_BL (3 * TILEB)

// ---------------- device scratch (no cudaMalloc allowed) ----------------
__device__ __nv_bfloat16 g_Xh[(size_t)MB_ * DIN_];
__device__ __nv_bfloat16 g_Xl[(size_t)MB_ * DIN_];
__device__ __nv_bfloat16 g_Uth[(size_t)RANK_ * DIN_];   // (U*diag(S))^T, [RANK, DIN]
__device__ __nv_bfloat16 g_Utl[(size_t)RANK_ * DIN_];
__device__ __nv_bfloat16 g_Vh[(size_t)UNITS_ * RANK_];  // V already [N, K]
__device__ __nv_bfloat16 g_Vl[(size_t)UNITS_ * RANK_];
__device__ __nv_bfloat16 g_Hh[(size_t)MB_ * RANK_];
__device__ __nv_bfloat16 g_Hl[(size_t)MB_ * RANK_];

// ---------------- helpers ----------------
__device__ __forceinline__ uint32_t su32(const void* p) {
    uint32_t a;
    asm("{ .reg .u64 t; cvta.to.shared.u64 t, %1; cvt.u32.u64 %0, t; }" : "=r"(a) : "l"(p));
    return a;
}
__device__ __forceinline__ void cp16(uint32_t d, const void* g) {
    asm volatile("cp.async.cg.shared.global [%0], [%1], 16;" :: "r"(d), "l"(g));
}
__device__ __forceinline__ void ldsm4(uint32_t& r0, uint32_t& r1, uint32_t& r2, uint32_t& r3,
                                      uint32_t addr) {
    asm volatile("ldmatrix.sync.aligned.m8n8.x4.shared.b16 {%0,%1,%2,%3}, [%4];"
                 : "=r"(r0), "=r"(r1), "=r"(r2), "=r"(r3) : "r"(addr));
}
__device__ __forceinline__ void mma16816(float* c, uint32_t a0, uint32_t a1, uint32_t a2,
                                         uint32_t a3, uint32_t b0, uint32_t b1) {
    asm volatile(
        "mma.sync.aligned.m16n8k16.row.col.f32.bf16.bf16.f32 "
        "{%0,%1,%2,%3}, {%4,%5,%6,%7}, {%8,%9}, {%0,%1,%2,%3};"
        : "+f"(c[0]), "+f"(c[1]), "+f"(c[2]), "+f"(c[3])
        : "r"(a0), "r"(a1), "r"(a2), "r"(a3), "r"(b0), "r"(b1));
}
__device__ __forceinline__ uint32_t pack_hi(float x, float y) {
    __nv_bfloat162 t(__float2bfloat16(x), __float2bfloat16(y));
    return *reinterpret_cast<uint32_t*>(&t);
}
__device__ __forceinline__ uint32_t pack_lo(float x, float y) {
    __nv_bfloat16 hx = __float2bfloat16(x), hy = __float2bfloat16(y);
    __nv_bfloat162 t(__float2bfloat16(x - __bfloat162float(hx)),
                     __float2bfloat16(y - __bfloat162float(hy)));
    return *reinterpret_cast<uint32_t*>(&t);
}

// ---------------- conversion kernels ----------------
__global__ void split_kernel(const float* __restrict__ src,
                             __nv_bfloat16* __restrict__ hi,
                             __nv_bfloat16* __restrict__ lo, int n4) {
    int i = blockIdx.x * blockDim.x + threadIdx.x;
    if (i >= n4) return;
    float4 v = reinterpret_cast<const float4*>(src)[i];
    uint2 hu = { pack_hi(v.x, v.y), pack_hi(v.z, v.w) };
    uint2 lu = { pack_lo(v.x, v.y), pack_lo(v.z, v.w) };
    reinterpret_cast<uint2*>(hi)[i] = hu;
    reinterpret_cast<uint2*>(lo)[i] = lu;
}

// Ut = (U * diag(S))^T split to bf16 hi/lo.  U: [DIN, RANK] row-major.
__global__ void uprep_kernel(const float* __restrict__ U, const float* __restrict__ S) {
    __shared__ float t[32][33];
    int n0 = blockIdx.x * 32, k0 = blockIdx.y * 32;
    int tx = threadIdx.x, ty = threadIdx.y;
    float sv = S[n0 + tx];
#pragma unroll
    for (int i = 0; i < 4; i++)
        t[ty + i * 8][tx] = U[(size_t)(k0 + ty + i * 8) * RANK_ + n0 + tx] * sv;
    __syncthreads();
#pragma unroll
    for (int i = 0; i < 4; i++) {
        int n = n0 + ty + i * 8, k = k0 + tx;
        float v = t[tx][ty + i * 8];
        __nv_bfloat16 h = __float2bfloat16(v);
        __nv_bfloat16 l = __float2bfloat16(v - __bfloat162float(h));
        g_Uth[(size_t)n * DIN_ + k] = h;
        g_Utl[(size_t)n * DIN_ + k] = l;
    }
}

// ---------------- GEMM ----------------
// 256 threads: each thread issues 2 cp16 per tile (128 rows x 4 segs = 512 ops/tile)
__device__ __forceinline__ void load_stage(uint32_t st,
                                           const __nv_bfloat16* a0, const __nv_bfloat16* a1,
                                           const __nv_bfloat16* b0, const __nv_bfloat16* b1,
                                           int K, int tid) {
#pragma unroll
    for (int i = 0; i < 2; i++) {
        const int op = tid + i * 256;
        const int r = op >> 2;           // 0..127
        const int seg = op & 3;          // 16B chunk of the 64B row
        const uint32_t so = (uint32_t)r * ROWB + seg * 16;
        const size_t go = (size_t)r * K + seg * 8;
        cp16(st + OFF_AH + so, a0 + go);
        cp16(st + OFF_AL + so, a1 + go);
        cp16(st + OFF_BH + so, b0 + go);
        cp16(st + OFF_BL + so, b1 + go);
    }
    asm volatile("cp.async.commit_group;" ::: "memory");
}

template <int MODE>
__global__ void __launch_bounds__(NTHR, 2)
gemm_kernel(const float* __restrict__ bias, float* __restrict__ out) {
    constexpr int K = (MODE == 0) ? DIN_ : RANK_;
    constexpr int NC = K / BK;

    extern __shared__ __align__(128) char smem[];
    const uint32_t sb = su32(smem);
    const int tid = threadIdx.x;
    const int lane = tid & 31;
    const int warp = tid >> 5;       // 0..7
    const int wm = warp >> 2;        // 0..1  (64-row slabs)
    const int wn = warp & 3;         // 0..3  (32-col slabs)
    const size_t m0 = (size_t)blockIdx.y * BM;
    const size_t n0 = (size_t)blockIdx.x * BN;

    const __nv_bfloat16 *Ah, *Al, *Bh, *Bl;
    if (MODE == 0) { Ah = g_Xh; Al = g_Xl; Bh = g_Uth; Bl = g_Utl; }
    else           { Ah = g_Hh; Al = g_Hl; Bh = g_Vh;  Bl = g_Vl;  }
    const __nv_bfloat16* a0 = Ah + m0 * K;
    const __nv_bfloat16* a1 = Al + m0 * K;
    const __nv_bfloat16* b0 = Bh + n0 * K;
    const __nv_bfloat16* b1 = Bl + n0 * K;

    load_stage(sb, a0, a1, b0, b1, K, tid);

    // warp tile 64x32: acc[mt 0..3][nt 0..3][4]
    float acc[4][4][4];
#pragma unroll
    for (int i = 0; i < 4; i++)
#pragma unroll
        for (int j = 0; j < 4; j++)
#pragma unroll
            for (int q = 0; q < 4; q++) acc[i][j][q] = 0.0f;

    const int lrow = lane & 15;
    const int lhalf = (lane >> 4) * 16;
    const uint32_t aLane = (uint32_t)(wm * 64 + lrow) * ROWB + lhalf;
    const uint32_t bLane = (uint32_t)(wn * 32 + lrow) * ROWB + lhalf;

    for (int c = 0; c < NC; c++) {
        asm volatile("cp.async.wait_group 0;" ::: "memory");
        __syncthreads();

        const uint32_t st = sb + (uint32_t)(c & 1) * STAGEB;
        if (c + 1 < NC) {
            const int kn = (c + 1) * BK;
            load_stage(sb + (uint32_t)((c + 1) & 1) * STAGEB,
                       a0 + kn, a1 + kn, b0 + kn, b1 + kn, K, tid);
        }

        const uint32_t aBase = st + aLane;
        const uint32_t bBase = st + bLane;

#pragma unroll
        for (int ks = 0; ks < 2; ks++) {
            const uint32_t ko = ks * 32;   // 16 bf16 per k-step
            uint32_t bh[8], bl[8];
            ldsm4(bh[0], bh[1], bh[2], bh[3], bBase + OFF_BH + ko);
            ldsm4(bh[4], bh[5], bh[6], bh[7], bBase + OFF_BH + 16 * ROWB + ko);
            ldsm4(bl[0], bl[1], bl[2], bl[3], bBase + OFF_BL + ko);
            ldsm4(bl[4], bl[5], bl[6], bl[7], bBase + OFF_BL + 16 * ROWB + ko);

#pragma unroll
            for (int mt = 0; mt < 4; mt++) {
                uint32_t ah[4], al[4];
                ldsm4(ah[0], ah[1], ah[2], ah[3], aBase + OFF_AH + (uint32_t)mt * 16 * ROWB + ko);
                ldsm4(al[0], al[1], al[2], al[3], aBase + OFF_AL + (uint32_t)mt * 16 * ROWB + ko);
#pragma unroll
                for (int nt = 0; nt < 4; nt++) {
                    const uint32_t bb0 = bh[(nt >> 1) * 4 + (nt & 1)];
                    const uint32_t bb1 = bh[(nt >> 1) * 4 + (nt & 1) + 2];
                    const uint32_t cb0 = bl[(nt >> 1) * 4 + (nt & 1)];
                    const uint32_t cb1 = bl[(nt >> 1) * 4 + (nt & 1) + 2];
                    float* cc = acc[mt][nt];
                    mma16816(cc, ah[0], ah[1], ah[2], ah[3], bb0, bb1);  // Ah*Bh
                    mma16816(cc, al[0], al[1], al[2], al[3], bb0, bb1);  // Al*Bh
                    mma16816(cc, ah[0], ah[1], ah[2], ah[3], cb0, cb1);  // Ah*Bl
                }
            }
        }
    }

    // ---------------- epilogue ----------------
    const int crow = lane >> 2;          // 0..7
    const int ccol = (lane & 3) * 2;     // 0,2,4,6
#pragma unroll
    for (int mt = 0; mt < 4; mt++) {
#pragma unroll
        for (int nt = 0; nt < 4; nt++) {
            const float* cc = acc[mt][nt];
            const size_t m = m0 + wm * 64 + mt * 16 + crow;
            const size_t n = n0 + wn * 32 + nt * 8 + ccol;
            if (MODE == 0) {
                *reinterpret_cast<uint32_t*>(g_Hh + m * RANK_ + n) = pack_hi(cc[0], cc[1]);
                *reinterpret_cast<uint32_t*>(g_Hl + m * RANK_ + n) = pack_lo(cc[0], cc[1]);
                *reinterpret_cast<uint32_t*>(g_Hh + (m + 8) * RANK_ + n) = pack_hi(cc[2], cc[3]);
                *reinterpret_cast<uint32_t*>(g_Hl + (m + 8) * RANK_ + n) = pack_lo(cc[2], cc[3]);
            } else {
                const float bv0 = __ldg(bias + n), bv1 = __ldg(bias + n + 1);
                float2 o0 = { fmaxf(cc[0] + bv0, 0.0f), fmaxf(cc[1] + bv1, 0.0f) };
                float2 o1 = { fmaxf(cc[2] + bv0, 0.0f), fmaxf(cc[3] + bv1, 0.0f) };
                *reinterpret_cast<float2*>(out + m * UNITS_ + n) = o0;
                *reinterpret_cast<float2*>(out + (m + 8) * UNITS_ + n) = o1;
            }
        }
    }
}

// ---------------- launch ----------------
extern "C" void kernel_launch(void* const* d_in, const int* in_sizes, int n_in,
                              void* d_out, int out_size) {
    const float* X    = (const float*)d_in[0];
    const float* U    = (const float*)d_in[1];
    const float* S    = (const float*)d_in[2];
    const float* V    = (const float*)d_in[3];
    const float* bias = (const float*)d_in[4];
    float* out = (float*)d_out;

    void *pXh, *pXl, *pVh, *pVl;
    cudaGetSymbolAddress(&pXh, g_Xh);
    cudaGetSymbolAddress(&pXl, g_Xl);
    cudaGetSymbolAddress(&pVh, g_Vh);
    cudaGetSymbolAddress(&pVl, g_Vl);

    split_kernel<<<(MB_ * DIN_ / 4 + 255) / 256, 256>>>(
        X, (__nv_bfloat16*)pXh, (__nv_bfloat16*)pXl, MB_ * DIN_ / 4);
    split_kernel<<<(UNITS_ * RANK_ / 4 + 255) / 256, 256>>>(
        V, (__nv_bfloat16*)pVh, (__nv_bfloat16*)pVl, UNITS_ * RANK_ / 4);
    uprep_kernel<<<dim3(RANK_ / 32, DIN_ / 32), dim3(32, 8)>>>(U, S);

    cudaFuncSetAttribute(gemm_kernel<0>, cudaFuncAttributeMaxDynamicSharedMemorySize, SMEMB);
    cudaFuncSetAttribute(gemm_kernel<1>, cudaFuncAttributeMaxDynamicSharedMemorySize, SMEMB);

    // GEMM1: H = (X @ U) * S  (S folded into U^T), split-stored to g_Hh/g_Hl
    gemm_kernel<0><<<dim3(RANK_ / BN, MB_ / BM), NTHR, SMEMB>>>(nullptr, nullptr);
    // GEMM2: out = relu(H @ V^T + bias)
    gemm_kernel<1><<<dim3(UNITS_ / BN, MB_ / BM), NTHR, SMEMB>>>(bias, out);
}